// round 4
// baseline (speedup 1.0000x reference)
#include <cuda_runtime.h>

typedef unsigned long long ull;

#define NWIN   4096
#define NTOK   49
#define DIMC   96
#define HEADS  3
#define HD     32
#define NWMASK 64

// smem layout (floats) — sw and sattn OVERLAP (never live together):
//  sx   [49*96]  = 4704    @ 0      (x, later attention output O)
//  sq   [3*49*32]= 4704    @ 4704
//  sk             4704     @ 9408
//  sv             4704     @ 14112
//  swk  max(96*100, 3*49*49) = 9600 @ 18816   (weights OR probs; tail = sinv)
#define SX_OFF  0
#define SQ_OFF  4704
#define SK_OFF  9408
#define SV_OFF  14112
#define SWK_OFF 18816
#define SINV_OFF (SWK_OFF + 7296)   // 147 floats in swk tail (free during softmax/AV)
#define SMEM_FLOATS 28416           // 113664 B -> 2 blocks/SM

__device__ __forceinline__ ull pack2(float lo, float hi) {
    ull r; asm("mov.b64 %0, {%1,%2};" : "=l"(r) : "f"(lo), "f"(hi)); return r;
}
__device__ __forceinline__ float2 u2f(ull v) {
    float2 f; asm("mov.b64 {%0,%1}, %2;" : "=f"(f.x), "=f"(f.y) : "l"(v)); return f;
}
__device__ __forceinline__ ull fma2(ull a, ull b, ull c) {
    ull d; asm("fma.rn.f32x2 %0, %1, %2, %3;" : "=l"(d) : "l"(a), "l"(b), "l"(c)); return d;
}
__device__ __forceinline__ ull add2(ull a, ull b) {
    ull d; asm("add.rn.f32x2 %0, %1, %2;" : "=l"(d) : "l"(a), "l"(b)); return d;
}

// 49x96 @ 96x96^T GEMM micro-kernel, packed f32x2 along k.
__device__ __forceinline__ void gemm_96(const float* __restrict__ sa,
                                        const float* __restrict__ swt,
                                        int r0, int tx, ull acc2[7][3])
{
    #pragma unroll
    for (int u = 0; u < 7; u++)
        #pragma unroll
        for (int n = 0; n < 3; n++) acc2[u][n] = 0ull;

    #pragma unroll
    for (int k4 = 0; k4 < 24; ++k4) {
        ulonglong2 a2[7];
        #pragma unroll
        for (int u = 0; u < 7; u++)
            a2[u] = *(const ulonglong2*)(sa + (r0 + u) * 96 + k4 * 4);
        ulonglong2 b2[3];
        #pragma unroll
        for (int n = 0; n < 3; n++)
            b2[n] = *(const ulonglong2*)(swt + (tx + 32 * n) * 100 + k4 * 4);
        #pragma unroll
        for (int u = 0; u < 7; u++)
            #pragma unroll
            for (int n = 0; n < 3; n++) {
                acc2[u][n] = fma2(a2[u].x, b2[n].x, acc2[u][n]);
                acc2[u][n] = fma2(a2[u].y, b2[n].y, acc2[u][n]);
            }
    }
}

__global__ __launch_bounds__(256, 2)
void win_attn_kernel(const float* __restrict__ x,
                     const float* __restrict__ mask,
                     const float* __restrict__ qkv_w,
                     const float* __restrict__ qkv_b,
                     const float* __restrict__ proj_w,
                     const float* __restrict__ proj_b,
                     const float* __restrict__ rpb,
                     const int*   __restrict__ rel_index,
                     float* __restrict__ out)
{
    extern __shared__ float sm[];
    float* sx   = sm + SX_OFF;
    float* sq   = sm + SQ_OFF;
    float* sk   = sm + SK_OFF;
    float* sv   = sm + SV_OFF;
    float* swk  = sm + SWK_OFF;
    float* sinv = sm + SINV_OFF;

    const int tid = threadIdx.x;
    const int bnw = blockIdx.x;
    const int w   = bnw & (NWMASK - 1);

    const int ty = tid >> 5;
    const int tx = tid & 31;
    const int r0 = ty * 7;
    const float scale = 0.17677669529663687f;  // 32^-0.5

    // ---- Stage 0: load x tile ----
    {
        const float4* xg  = (const float4*)(x + (size_t)bnw * (NTOK * DIMC));
        float4* sx4 = (float4*)sx;
        #pragma unroll 2
        for (int e = tid; e < (NTOK * DIMC) / 4; e += 256) sx4[e] = xg[e];
    }
    __syncthreads();

    // ---- Stage 1: qkv GEMM (three 96-col slices), packed f32x2 ----
    for (int slice = 0; slice < 3; ++slice) {
        const float4* wg = (const float4*)(qkv_w + slice * 96 * 96);
        for (int e = tid; e < 96 * 24; e += 256) {
            int row = e / 24, c4 = e - row * 24;
            ((float4*)(swk + row * 100))[c4] = wg[e];
        }
        __syncthreads();

        ull acc2[7][3];
        gemm_96(sx, swk, r0, tx, acc2);

        float* dst = (slice == 0) ? sq : (slice == 1) ? sk : sv;
        const float mul = (slice == 0) ? scale : 1.f;
        #pragma unroll
        for (int n = 0; n < 3; n++) {
            int c = tx + 32 * n;
            float bias = qkv_b[slice * 96 + c];
            int h = c >> 5, d = c & 31;
            #pragma unroll
            for (int u = 0; u < 7; u++) {
                int rr = r0 + u;
                if (rr < NTOK) {
                    float2 f = u2f(acc2[u][n]);
                    dst[h * (NTOK * HD) + rr * HD + d] = (f.x + f.y + bias) * mul;
                }
            }
        }
        __syncthreads();
    }

    // ---- Stage 2: logits (bias+mask via LDG) + sign-softmax ----
    if (tid < HEADS * NTOK) {
        const int h = tid / NTOK;
        const int i = tid - h * NTOK;
        const ulonglong2* q2 = (const ulonglong2*)(sq + h * (NTOK * HD) + i * HD);
        ulonglong2 qp[8];
        #pragma unroll
        for (int t = 0; t < 8; t++) qp[t] = q2[t];

        float* arow = swk + h * (NTOK * NTOK) + i * NTOK;
        const float* mrow = mask + w * (NTOK * NTOK) + i * NTOK;
        const int*   rrow = rel_index + i * NTOK;
        const float* kbase = sk + h * (NTOK * HD);

        float mx0 = 0.f, mx1 = 0.f;
        #pragma unroll 7
        for (int j = 0; j < NTOK; j++) {
            float bm = __ldg(&rpb[__ldg(&rrow[j]) * HEADS + h]) + __ldg(&mrow[j]);
            const ulonglong2* k2 = (const ulonglong2*)(kbase + j * HD);
            ull a0 = 0ull, a1 = 0ull, a2 = 0ull, a3 = 0ull;
            #pragma unroll
            for (int t = 0; t < 8; t += 2) {
                ulonglong2 kva = k2[t];
                ulonglong2 kvb = k2[t + 1];
                a0 = fma2(qp[t].x,     kva.x, a0);
                a1 = fma2(qp[t].y,     kva.y, a1);
                a2 = fma2(qp[t + 1].x, kvb.x, a2);
                a3 = fma2(qp[t + 1].y, kvb.y, a3);
            }
            float2 f = u2f(add2(add2(a0, a1), add2(a2, a3)));
            float a = f.x + f.y + bm;
            arow[j] = a;
            if (j & 1) mx1 = fmaxf(mx1, fabsf(a));
            else       mx0 = fmaxf(mx0, fabsf(a));
        }
        float mx = fmaxf(mx0, mx1);

        float s0 = 0.f, s1 = 0.f;
        #pragma unroll 7
        for (int j = 0; j < NTOK; j++) {
            float a = arow[j];
            float e = __expf(fabsf(a) - mx);
            if (j & 1) s1 += e;
            else       s0 += e;
            arow[j] = (a > 0.f) ? e : ((a < 0.f) ? -e : 0.f);
        }
        sinv[tid] = 1.f / (s0 + s1);
    }
    __syncthreads();

    // ---- Stage 3: AV -> O into sx (x is dead), scale by 1/s at the end ----
    {
        float4* sao4 = (float4*)sx;
        #pragma unroll 2
        for (int e = tid; e < (NTOK * DIMC) / 4; e += 256) {
            int i = e / 24, g = e - i * 24;
            int h = g >> 3, d4 = g & 7;
            const float* prow  = swk + h * (NTOK * NTOK) + i * NTOK;
            const float* vbase = sv + h * (NTOK * HD) + d4 * 4;
            ull acc0 = 0ull, acc1 = 0ull, acc2 = 0ull, acc3 = 0ull;
            #pragma unroll
            for (int j = 0; j < NTOK - 1; j += 2) {
                float p0 = prow[j], p1 = prow[j + 1];
                ulonglong2 v0 = *(const ulonglong2*)(vbase + j * HD);
                ulonglong2 v1 = *(const ulonglong2*)(vbase + (j + 1) * HD);
                ull pp0 = pack2(p0, p0), pp1 = pack2(p1, p1);
                acc0 = fma2(pp0, v0.x, acc0);
                acc1 = fma2(pp0, v0.y, acc1);
                acc2 = fma2(pp1, v1.x, acc2);
                acc3 = fma2(pp1, v1.y, acc3);
            }
            {   // peel j = 48
                float p = prow[NTOK - 1];
                ulonglong2 vv = *(const ulonglong2*)(vbase + (NTOK - 1) * HD);
                ull pp = pack2(p, p);
                acc0 = fma2(pp, vv.x, acc0);
                acc1 = fma2(pp, vv.y, acc1);
            }
            float inv = sinv[h * NTOK + i];
            float2 lo = u2f(add2(acc0, acc2));
            float2 hi = u2f(add2(acc1, acc3));
            sao4[e] = make_float4(lo.x * inv, lo.y * inv, hi.x * inv, hi.y * inv);
        }
    }
    __syncthreads();

    // ---- Stage 4: projection GEMM (weights overwrite probs — dead) ----
    {
        const float4* wg = (const float4*)proj_w;
        for (int e = tid; e < 96 * 24; e += 256) {
            int row = e / 24, c4 = e - row * 24;
            ((float4*)(swk + row * 100))[c4] = wg[e];
        }
        __syncthreads();

        ull acc2[7][3];
        gemm_96(sx, swk, r0, tx, acc2);

        float* og = out + (size_t)bnw * (NTOK * DIMC);
        #pragma unroll
        for (int n = 0; n < 3; n++) {
            int c = tx + 32 * n;
            float pb = proj_b[c];
            #pragma unroll
            for (int u = 0; u < 7; u++) {
                int rr = r0 + u;
                if (rr < NTOK) {
                    float2 f = u2f(acc2[u][n]);
                    og[rr * DIMC + c] = f.x + f.y + pb;
                }
            }
        }
    }
}

extern "C" void kernel_launch(void* const* d_in, const int* in_sizes, int n_in,
                              void* d_out, int out_size) {
    const float* x      = (const float*)d_in[0];
    const float* mask   = (const float*)d_in[1];
    const float* qkv_w  = (const float*)d_in[2];
    const float* qkv_b  = (const float*)d_in[3];
    const float* proj_w = (const float*)d_in[4];
    const float* proj_b = (const float*)d_in[5];
    const float* rpb    = (const float*)d_in[6];
    const int*   relidx = (const int*)d_in[7];
    float* out = (float*)d_out;

    const int smem_bytes = SMEM_FLOATS * (int)sizeof(float);
    cudaFuncSetAttribute(win_attn_kernel,
                         cudaFuncAttributeMaxDynamicSharedMemorySize, smem_bytes);
    win_attn_kernel<<<NWIN, 256, smem_bytes>>>(x, mask, qkv_w, qkv_b,
                                               proj_w, proj_b, rpb, relidx, out);
}

// round 5
// speedup vs baseline: 1.0004x; 1.0004x over previous
#include <cuda_runtime.h>

typedef unsigned long long ull;

#define NWIN   4096
#define NTOK   49
#define DIMC   96
#define HEADS  3
#define HD     32
#define NWMASK 64

// smem layout (floats) — sw and sattn OVERLAP (never live together):
//  sx   [49*96]  = 4704    @ 0      (x, later attention output O)
//  sq   [3*49*32]= 4704    @ 4704
//  sk             4704     @ 9408
//  sv             4704     @ 14112
//  swk  max(96*100, 3*49*49) = 9600 @ 18816   (weights OR probs; tail = sinv)
#define SX_OFF  0
#define SQ_OFF  4704
#define SK_OFF  9408
#define SV_OFF  14112
#define SWK_OFF 18816
#define SINV_OFF (SWK_OFF + 7296)   // 147 floats in swk tail (free during softmax/AV)
#define SMEM_FLOATS 28416           // 113664 B -> 2 blocks/SM

__device__ __forceinline__ ull pack2(float lo, float hi) {
    ull r; asm("mov.b64 %0, {%1,%2};" : "=l"(r) : "f"(lo), "f"(hi)); return r;
}
__device__ __forceinline__ float2 u2f(ull v) {
    float2 f; asm("mov.b64 {%0,%1}, %2;" : "=f"(f.x), "=f"(f.y) : "l"(v)); return f;
}
__device__ __forceinline__ ull fma2(ull a, ull b, ull c) {
    ull d; asm("fma.rn.f32x2 %0, %1, %2, %3;" : "=l"(d) : "l"(a), "l"(b), "l"(c)); return d;
}
__device__ __forceinline__ ull add2(ull a, ull b) {
    ull d; asm("add.rn.f32x2 %0, %1, %2;" : "=l"(d) : "l"(a), "l"(b)); return d;
}

// 49x96 @ 96x96^T GEMM micro-kernel, packed f32x2 along k.
__device__ __forceinline__ void gemm_96(const float* __restrict__ sa,
                                        const float* __restrict__ swt,
                                        int r0, int tx, ull acc2[7][3])
{
    #pragma unroll
    for (int u = 0; u < 7; u++)
        #pragma unroll
        for (int n = 0; n < 3; n++) acc2[u][n] = 0ull;

    #pragma unroll
    for (int k4 = 0; k4 < 24; ++k4) {
        ulonglong2 a2[7];
        #pragma unroll
        for (int u = 0; u < 7; u++)
            a2[u] = *(const ulonglong2*)(sa + (r0 + u) * 96 + k4 * 4);
        ulonglong2 b2[3];
        #pragma unroll
        for (int n = 0; n < 3; n++)
            b2[n] = *(const ulonglong2*)(swt + (tx + 32 * n) * 100 + k4 * 4);
        #pragma unroll
        for (int u = 0; u < 7; u++)
            #pragma unroll
            for (int n = 0; n < 3; n++) {
                acc2[u][n] = fma2(a2[u].x, b2[n].x, acc2[u][n]);
                acc2[u][n] = fma2(a2[u].y, b2[n].y, acc2[u][n]);
            }
    }
}

__global__ __launch_bounds__(256, 2)
void win_attn_kernel(const float* __restrict__ x,
                     const float* __restrict__ mask,
                     const float* __restrict__ qkv_w,
                     const float* __restrict__ qkv_b,
                     const float* __restrict__ proj_w,
                     const float* __restrict__ proj_b,
                     const float* __restrict__ rpb,
                     const int*   __restrict__ rel_index,
                     float* __restrict__ out)
{
    extern __shared__ float sm[];
    float* sx   = sm + SX_OFF;
    float* sq   = sm + SQ_OFF;
    float* sk   = sm + SK_OFF;
    float* sv   = sm + SV_OFF;
    float* swk  = sm + SWK_OFF;
    float* sinv = sm + SINV_OFF;

    const int tid = threadIdx.x;
    const int bnw = blockIdx.x;
    const int w   = bnw & (NWMASK - 1);

    const int ty = tid >> 5;
    const int tx = tid & 31;
    const int r0 = ty * 7;
    const float scale = 0.17677669529663687f;  // 32^-0.5

    // ---- Stage 0: load x tile ----
    {
        const float4* xg  = (const float4*)(x + (size_t)bnw * (NTOK * DIMC));
        float4* sx4 = (float4*)sx;
        #pragma unroll 2
        for (int e = tid; e < (NTOK * DIMC) / 4; e += 256) sx4[e] = xg[e];
    }
    __syncthreads();

    // ---- Stage 1: qkv GEMM (three 96-col slices), packed f32x2 ----
    for (int slice = 0; slice < 3; ++slice) {
        const float4* wg = (const float4*)(qkv_w + slice * 96 * 96);
        for (int e = tid; e < 96 * 24; e += 256) {
            int row = e / 24, c4 = e - row * 24;
            ((float4*)(swk + row * 100))[c4] = wg[e];
        }
        __syncthreads();

        ull acc2[7][3];
        gemm_96(sx, swk, r0, tx, acc2);

        float* dst = (slice == 0) ? sq : (slice == 1) ? sk : sv;
        const float mul = (slice == 0) ? scale : 1.f;
        #pragma unroll
        for (int n = 0; n < 3; n++) {
            int c = tx + 32 * n;
            float bias = qkv_b[slice * 96 + c];
            int h = c >> 5, d = c & 31;
            #pragma unroll
            for (int u = 0; u < 7; u++) {
                int rr = r0 + u;
                if (rr < NTOK) {
                    float2 f = u2f(acc2[u][n]);
                    dst[h * (NTOK * HD) + rr * HD + d] = (f.x + f.y + bias) * mul;
                }
            }
        }
        __syncthreads();
    }

    // ---- Stage 2: logits (bias+mask via LDG) + sign-softmax ----
    if (tid < HEADS * NTOK) {
        const int h = tid / NTOK;
        const int i = tid - h * NTOK;
        const ulonglong2* q2 = (const ulonglong2*)(sq + h * (NTOK * HD) + i * HD);
        ulonglong2 qp[8];
        #pragma unroll
        for (int t = 0; t < 8; t++) qp[t] = q2[t];

        float* arow = swk + h * (NTOK * NTOK) + i * NTOK;
        const float* mrow = mask + w * (NTOK * NTOK) + i * NTOK;
        const int*   rrow = rel_index + i * NTOK;
        const float* kbase = sk + h * (NTOK * HD);

        float mx0 = 0.f, mx1 = 0.f;
        #pragma unroll 7
        for (int j = 0; j < NTOK; j++) {
            float bm = __ldg(&rpb[__ldg(&rrow[j]) * HEADS + h]) + __ldg(&mrow[j]);
            const ulonglong2* k2 = (const ulonglong2*)(kbase + j * HD);
            ull a0 = 0ull, a1 = 0ull, a2 = 0ull, a3 = 0ull;
            #pragma unroll
            for (int t = 0; t < 8; t += 2) {
                ulonglong2 kva = k2[t];
                ulonglong2 kvb = k2[t + 1];
                a0 = fma2(qp[t].x,     kva.x, a0);
                a1 = fma2(qp[t].y,     kva.y, a1);
                a2 = fma2(qp[t + 1].x, kvb.x, a2);
                a3 = fma2(qp[t + 1].y, kvb.y, a3);
            }
            float2 f = u2f(add2(add2(a0, a1), add2(a2, a3)));
            float a = f.x + f.y + bm;
            arow[j] = a;
            if (j & 1) mx1 = fmaxf(mx1, fabsf(a));
            else       mx0 = fmaxf(mx0, fabsf(a));
        }
        float mx = fmaxf(mx0, mx1);

        float s0 = 0.f, s1 = 0.f;
        #pragma unroll 7
        for (int j = 0; j < NTOK; j++) {
            float a = arow[j];
            float e = __expf(fabsf(a) - mx);
            if (j & 1) s1 += e;
            else       s0 += e;
            arow[j] = (a > 0.f) ? e : ((a < 0.f) ? -e : 0.f);
        }
        sinv[tid] = 1.f / (s0 + s1);
    }
    __syncthreads();

    // ---- Stage 3: AV -> O into sx (x is dead), scale by 1/s at the end ----
    {
        float4* sao4 = (float4*)sx;
        #pragma unroll 2
        for (int e = tid; e < (NTOK * DIMC) / 4; e += 256) {
            int i = e / 24, g = e - i * 24;
            int h = g >> 3, d4 = g & 7;
            const float* prow  = swk + h * (NTOK * NTOK) + i * NTOK;
            const float* vbase = sv + h * (NTOK * HD) + d4 * 4;
            ull acc0 = 0ull, acc1 = 0ull, acc2 = 0ull, acc3 = 0ull;
            #pragma unroll
            for (int j = 0; j < NTOK - 1; j += 2) {
                float p0 = prow[j], p1 = prow[j + 1];
                ulonglong2 v0 = *(const ulonglong2*)(vbase + j * HD);
                ulonglong2 v1 = *(const ulonglong2*)(vbase + (j + 1) * HD);
                ull pp0 = pack2(p0, p0), pp1 = pack2(p1, p1);
                acc0 = fma2(pp0, v0.x, acc0);
                acc1 = fma2(pp0, v0.y, acc1);
                acc2 = fma2(pp1, v1.x, acc2);
                acc3 = fma2(pp1, v1.y, acc3);
            }
            {   // peel j = 48
                float p = prow[NTOK - 1];
                ulonglong2 vv = *(const ulonglong2*)(vbase + (NTOK - 1) * HD);
                ull pp = pack2(p, p);
                acc0 = fma2(pp, vv.x, acc0);
                acc1 = fma2(pp, vv.y, acc1);
            }
            float inv = sinv[h * NTOK + i];
            float2 lo = u2f(add2(acc0, acc2));
            float2 hi = u2f(add2(acc1, acc3));
            sao4[e] = make_float4(lo.x * inv, lo.y * inv, hi.x * inv, hi.y * inv);
        }
    }
    __syncthreads();

    // ---- Stage 4: projection GEMM (weights overwrite probs — dead) ----
    {
        const float4* wg = (const float4*)proj_w;
        for (int e = tid; e < 96 * 24; e += 256) {
            int row = e / 24, c4 = e - row * 24;
            ((float4*)(swk + row * 100))[c4] = wg[e];
        }
        __syncthreads();

        ull acc2[7][3];
        gemm_96(sx, swk, r0, tx, acc2);

        float* og = out + (size_t)bnw * (NTOK * DIMC);
        #pragma unroll
        for (int n = 0; n < 3; n++) {
            int c = tx + 32 * n;
            float pb = proj_b[c];
            #pragma unroll
            for (int u = 0; u < 7; u++) {
                int rr = r0 + u;
                if (rr < NTOK) {
                    float2 f = u2f(acc2[u][n]);
                    og[rr * DIMC + c] = f.x + f.y + pb;
                }
            }
        }
    }
}

extern "C" void kernel_launch(void* const* d_in, const int* in_sizes, int n_in,
                              void* d_out, int out_size) {
    const float* x      = (const float*)d_in[0];
    const float* mask   = (const float*)d_in[1];
    const float* qkv_w  = (const float*)d_in[2];
    const float* qkv_b  = (const float*)d_in[3];
    const float* proj_w = (const float*)d_in[4];
    const float* proj_b = (const float*)d_in[5];
    const float* rpb    = (const float*)d_in[6];
    const int*   relidx = (const int*)d_in[7];
    float* out = (float*)d_out;

    const int smem_bytes = SMEM_FLOATS * (int)sizeof(float);
    cudaFuncSetAttribute(win_attn_kernel,
                         cudaFuncAttributeMaxDynamicSharedMemorySize, smem_bytes);
    win_attn_kernel<<<NWIN, 256, smem_bytes>>>(x, mask, qkv_w, qkv_b,
                                               proj_w, proj_b, rpb, relidx, out);
}